// round 2
// baseline (speedup 1.0000x reference)
#include <cuda_runtime.h>
#include <math.h>

// QuantumTransformerBlock — closed-form quantum ops + f-pair-packed f32x2 FFN.
// B=32, S=2048, E=8, F=2048 -> N=65536 tokens, 1 token/thread, 512 thr/block, 128 blocks.

#define N_TOK 65536
// smem floats: W1i [1024 fp][8 j] pairs = 16384 f | W2i [1024 fp][10 pad] pairs = 20480 f | b1 pairs 2048 f
#define SMEM_FLOATS (16384 + 20480 + 2048)
#define SMEM_BYTES  (SMEM_FLOATS * 4)   // 155648

typedef unsigned long long u64;

__device__ __forceinline__ u64 fma2(u64 a, u64 b, u64 c) {
    u64 d; asm("fma.rn.f32x2 %0, %1, %2, %3;" : "=l"(d) : "l"(a), "l"(b), "l"(c)); return d;
}
__device__ __forceinline__ u64 mul2(u64 a, u64 b) {
    u64 d; asm("mul.rn.f32x2 %0, %1, %2;" : "=l"(d) : "l"(a), "l"(b)); return d;
}
__device__ __forceinline__ u64 add2(u64 a, u64 b) {
    u64 d; asm("add.rn.f32x2 %0, %1, %2;" : "=l"(d) : "l"(a), "l"(b)); return d;
}
__device__ __forceinline__ void unpack2(u64 a, float& lo, float& hi) {
    asm("mov.b64 {%0, %1}, %2;" : "=f"(lo), "=f"(hi) : "l"(a));
}
__device__ __forceinline__ u64 pack2(float lo, float hi) {
    u64 d; asm("mov.b64 %0, {%1, %2};" : "=l"(d) : "f"(lo), "f"(hi)); return d;
}

__global__ void __launch_bounds__(512, 1) qtb_kernel(
    const float* __restrict__ x, const float* __restrict__ theta, const float* __restrict__ phi,
    const float* __restrict__ W1, const float* __restrict__ b1,
    const float* __restrict__ W2, const float* __restrict__ b2,
    const float* __restrict__ g1, const float* __restrict__ be1,
    const float* __restrict__ g2, const float* __restrict__ be2,
    float* __restrict__ out)
{
    extern __shared__ float smem[];
    float2* sW1i = (float2*)smem;                   // pair idx = fp*8 + j
    float2* sW2i = (float2*)(smem + 16384);         // pair idx = fp*10 + e (80B row stride)
    float2* sB1i = (float2*)(smem + 36864);         // pair idx = fp

    const int tid = threadIdx.x;

    // ---- preamble: build interleaved f-pair weight tables ----
    for (int i = tid; i < 8192; i += 512) {
        int fp = i >> 3, j = i & 7;
        sW1i[i] = make_float2(W1[(fp << 4) + j], W1[(fp << 4) + 8 + j]);
    }
    for (int i = tid; i < 8192; i += 512) {
        int fp = i & 1023, e = i >> 10;
        float2 v = *(const float2*)(W2 + (e << 11) + (fp << 1));  // (W2[e][2fp], W2[e][2fp+1])
        sW2i[fp * 10 + e] = v;
    }
    for (int i = tid; i < 1024; i += 512)
        sB1i[i] = ((const float2*)b1)[i];
    __syncthreads();

    const int t = blockIdx.x * 512 + tid;           // one token per thread, exact fit

    // broadcast params
    float th[8], cph[8], gg[8], bb[8];
    #pragma unroll
    for (int j = 0; j < 8; j++) {
        th[j]  = __ldg(theta + j);
        cph[j] = cosf(__ldg(phi + j));
        gg[j]  = __ldg(g1 + j);
        bb[j]  = __ldg(be1 + j);
    }

    // ---- closed-form attn + layernorm1 + ffn_quantum ----
    const float* xp = x + (size_t)t * 8;
    float4 a4 = __ldg((const float4*)xp);
    float4 b4 = __ldg((const float4*)(xp + 4));
    float xv[8] = {a4.x, a4.y, a4.z, a4.w, b4.x, b4.y, b4.z, b4.w};

    float c[8];
    #pragma unroll
    for (int j = 0; j < 8; j++) c[j] = cosf(xv[j] + th[j]);
    float attn[8];
    float p0 = c[0];
    #pragma unroll
    for (int j = 1; j < 8; j++) { p0 *= c[j]; attn[j] = p0; }
    float q0 = c[1];
    #pragma unroll
    for (int j = 2; j < 8; j++) q0 *= c[j];
    attn[0] = q0;

    float y[8]; float s = 0.f;
    #pragma unroll
    for (int j = 0; j < 8; j++) { y[j] = xv[j] + attn[j]; s += y[j]; }
    float m = s * 0.125f, v = 0.f;
    #pragma unroll
    for (int j = 0; j < 8; j++) { float d = y[j] - m; v += d * d; }
    float inv = rsqrtf(v * 0.125f + 1e-5f);

    float h[8];
    u64 zz[8];
    #pragma unroll
    for (int j = 0; j < 8; j++) {
        h[j] = (y[j] - m) * inv * gg[j] + bb[j];
        float z = cph[j] * cosf(h[j]);
        zz[j] = pack2(z, z);                        // replicated pair
    }

    // ---- fused FFN over f-pairs ----
    u64 acc[8] = {0,0,0,0,0,0,0,0};                 // acc[e] = (sum over f0-lane, f1-lane)
    const ulonglong2* w1 = (const ulonglong2*)sW1i; // 4 per fp
    const u64*        bp1 = (const u64*)sB1i;
    const u64*        w2  = (const u64*)sW2i;       // row stride 10

    #pragma unroll 2
    for (int fp = 0; fp < 1024; fp++) {
        const ulonglong2* wa = w1 + (fp << 2);
        ulonglong2 A0 = wa[0], A1 = wa[1], A2 = wa[2], A3 = wa[3];
        u64 bp = bp1[fp];

        u64 p = fma2(zz[0], A0.x, bp);              // chain 1 (init = bias pair)
        u64 q = mul2(zz[4], A2.x);                  // chain 2
        p = fma2(zz[1], A0.y, p);
        q = fma2(zz[5], A2.y, q);
        p = fma2(zz[2], A1.x, p);
        q = fma2(zz[6], A3.x, q);
        p = fma2(zz[3], A1.y, p);
        q = fma2(zz[7], A3.y, q);
        u64 sdot = add2(p, q);                      // (dot_f0+b, dot_f1+b)

        float lo, hi; unpack2(sdot, lo, hi);
        lo = fmaxf(lo, 0.0f);                       // FMNMX on ALU pipe
        hi = fmaxf(hi, 0.0f);
        u64 r = pack2(lo, hi);

        const ulonglong2* wb = (const ulonglong2*)(w2 + fp * 10);
        ulonglong2 C0 = wb[0], C1 = wb[1], C2 = wb[2], C3 = wb[3];
        acc[0] = fma2(r, C0.x, acc[0]);
        acc[1] = fma2(r, C0.y, acc[1]);
        acc[2] = fma2(r, C1.x, acc[2]);
        acc[3] = fma2(r, C1.y, acc[3]);
        acc[4] = fma2(r, C2.x, acc[4]);
        acc[5] = fma2(r, C2.y, acc[5]);
        acc[6] = fma2(r, C3.x, acc[6]);
        acc[7] = fma2(r, C3.y, acc[7]);
    }

    // ---- epilogue: residual + layernorm2 ----
    float w[8]; float s2 = 0.f;
    #pragma unroll
    for (int e = 0; e < 8; e++) {
        float lo, hi; unpack2(acc[e], lo, hi);
        w[e] = h[e] + (lo + hi) + __ldg(b2 + e);
        s2 += w[e];
    }
    float m2 = s2 * 0.125f, v2 = 0.f;
    #pragma unroll
    for (int e = 0; e < 8; e++) { float d = w[e] - m2; v2 += d * d; }
    float inv2 = rsqrtf(v2 * 0.125f + 1e-5f);
    float o[8];
    #pragma unroll
    for (int e = 0; e < 8; e++)
        o[e] = (w[e] - m2) * inv2 * __ldg(g2 + e) + __ldg(be2 + e);

    float* op = out + (size_t)t * 8;
    *(float4*)op       = make_float4(o[0], o[1], o[2], o[3]);
    *(float4*)(op + 4) = make_float4(o[4], o[5], o[6], o[7]);
}

extern "C" void kernel_launch(void* const* d_in, const int* in_sizes, int n_in,
                              void* d_out, int out_size) {
    const float* x      = (const float*)d_in[0];
    const float* theta  = (const float*)d_in[1];
    const float* phi    = (const float*)d_in[2];
    const float* W1     = (const float*)d_in[3];
    const float* b1     = (const float*)d_in[4];
    const float* W2     = (const float*)d_in[5];
    const float* b2     = (const float*)d_in[6];
    const float* gamma1 = (const float*)d_in[7];
    const float* beta1  = (const float*)d_in[8];
    const float* gamma2 = (const float*)d_in[9];
    const float* beta2  = (const float*)d_in[10];
    float* out = (float*)d_out;

    cudaFuncSetAttribute(qtb_kernel, cudaFuncAttributeMaxDynamicSharedMemorySize, SMEM_BYTES);
    qtb_kernel<<<128, 512, SMEM_BYTES>>>(x, theta, phi, W1, b1, W2, b2,
                                         gamma1, beta1, gamma2, beta2, out);
}

// round 4
// speedup vs baseline: 1.3505x; 1.3505x over previous
#include <cuda_runtime.h>
#include <math.h>

// QuantumTransformerBlock — closed-form quantum ops + f-split, token-amortized f32x2 FFN.
// B=32,S=2048,E=8,F=2048 -> 65536 tokens. 128 blocks x 512 threads.
// Warps 0-7: f in [0,1024); warps 8-15: f in [1024,2048). Each thread: 2 tokens, half f-range.

#define SMEM_BYTES 139264   // 34816 floats: W1i 16384 + W2i 16384 + b1 2048

typedef unsigned long long u64;

__device__ __forceinline__ u64 fma2(u64 a, u64 b, u64 c) {
    u64 d; asm("fma.rn.f32x2 %0, %1, %2, %3;" : "=l"(d) : "l"(a), "l"(b), "l"(c)); return d;
}
__device__ __forceinline__ u64 mul2(u64 a, u64 b) {
    u64 d; asm("mul.rn.f32x2 %0, %1, %2;" : "=l"(d) : "l"(a), "l"(b)); return d;
}
__device__ __forceinline__ u64 add2(u64 a, u64 b) {
    u64 d; asm("add.rn.f32x2 %0, %1, %2;" : "=l"(d) : "l"(a), "l"(b)); return d;
}
__device__ __forceinline__ void unpack2(u64 a, float& lo, float& hi) {
    asm("mov.b64 {%0, %1}, %2;" : "=f"(lo), "=f"(hi) : "l"(a));
}
__device__ __forceinline__ u64 pack2(float lo, float hi) {
    u64 d; asm("mov.b64 %0, {%1, %2};" : "=l"(d) : "f"(lo), "f"(hi)); return d;
}

__global__ void __launch_bounds__(512, 1) qtb_kernel(
    const float* __restrict__ x, const float* __restrict__ theta, const float* __restrict__ phi,
    const float* __restrict__ W1, const float* __restrict__ b1,
    const float* __restrict__ W2, const float* __restrict__ b2,
    const float* __restrict__ g1, const float* __restrict__ be1,
    const float* __restrict__ g2, const float* __restrict__ be2,
    float* __restrict__ out)
{
    extern __shared__ float smem[];
    float2* sW1i = (float2*)smem;                   // floats [0,16384): [1024 fp][8 j] pairs
    float2* sW2i = (float2*)(smem + 16384);         // floats [16384,32768): [1024 fp][8 e] pairs
    float2* sB1p = (float2*)(smem + 32768);         // floats [32768,34816): [1024 fp] pairs

    const int tid = threadIdx.x;

    // ---- preamble: interleaved f-pair weight tables ----
    for (int i = tid; i < 8192; i += 512) {
        int fp = i >> 3, j = i & 7;
        sW1i[i] = make_float2(W1[(fp << 4) + j], W1[(fp << 4) + 8 + j]);
    }
    for (int i = tid; i < 8192; i += 512) {
        int fp = i & 1023, e = i >> 10;
        sW2i[(fp << 3) + e] = *(const float2*)(W2 + (e << 11) + (fp << 1));
    }
    for (int i = tid; i < 1024; i += 512)
        sB1p[i] = ((const float2*)b1)[i];
    __syncthreads();

    const int half = tid >> 8;                      // 0: f[0,1024), 1: f[1024,2048)
    const int p    = tid & 255;                     // token-pair id within block
    const int t0   = blockIdx.x * 512 + (p << 1);   // 2 adjacent tokens

    // broadcast params
    float th[8], cph[8], gg[8], bb[8];
    #pragma unroll
    for (int j = 0; j < 8; j++) {
        th[j]  = __ldg(theta + j);
        cph[j] = cosf(__ldg(phi + j));
        gg[j]  = __ldg(g1 + j);
        bb[j]  = __ldg(be1 + j);
    }

    // ---- front: closed-form attn + LN1 + ffn_quantum (both tokens) ----
    float h0[8], h1[8];
    u64 zz0[8], zz1[8];
    #pragma unroll
    for (int tk = 0; tk < 2; tk++) {
        const float* xp = x + (size_t)(t0 + tk) * 8;
        float4 a4 = __ldg((const float4*)xp);
        float4 b4 = __ldg((const float4*)(xp + 4));
        float xv[8] = {a4.x, a4.y, a4.z, a4.w, b4.x, b4.y, b4.z, b4.w};

        float c[8];
        #pragma unroll
        for (int j = 0; j < 8; j++) c[j] = cosf(xv[j] + th[j]);
        float attn[8];
        float pr = c[0];
        #pragma unroll
        for (int j = 1; j < 8; j++) { pr *= c[j]; attn[j] = pr; }
        float qr = c[1];
        #pragma unroll
        for (int j = 2; j < 8; j++) qr *= c[j];
        attn[0] = qr;

        float y[8]; float s = 0.f;
        #pragma unroll
        for (int j = 0; j < 8; j++) { y[j] = xv[j] + attn[j]; s += y[j]; }
        float m = s * 0.125f, v = 0.f;
        #pragma unroll
        for (int j = 0; j < 8; j++) { float d = y[j] - m; v += d * d; }
        float inv = rsqrtf(v * 0.125f + 1e-5f);

        float* hh = tk ? h1 : h0;
        u64*   zz = tk ? zz1 : zz0;
        #pragma unroll
        for (int j = 0; j < 8; j++) {
            hh[j] = (y[j] - m) * inv * gg[j] + bb[j];
            float z = cph[j] * cosf(hh[j]);
            zz[j] = pack2(z, z);
        }
    }

    // ---- FFN over this half's 512 f-pairs, 2 tokens per thread ----
    u64 acc0[8] = {0,0,0,0,0,0,0,0};
    u64 acc1[8] = {0,0,0,0,0,0,0,0};
    {
        const int fpbase = half << 9;               // 0 or 512
        const ulonglong2* w1 = (const ulonglong2*)sW1i + ((size_t)fpbase << 2);
        const ulonglong2* w2 = (const ulonglong2*)sW2i + ((size_t)fpbase << 2);
        const u64*        bp = (const u64*)sB1p + fpbase;

        #pragma unroll 2
        for (int fp = 0; fp < 512; fp++) {
            ulonglong2 A0 = w1[0], A1 = w1[1], A2 = w1[2], A3 = w1[3]; w1 += 4;
            u64 bpv = bp[fp];

            u64 pA = fma2(zz0[0], A0.x, bpv);
            u64 pB = mul2(zz0[4], A2.x);
            u64 qA = fma2(zz1[0], A0.x, bpv);
            u64 qB = mul2(zz1[4], A2.x);
            pA = fma2(zz0[1], A0.y, pA);
            pB = fma2(zz0[5], A2.y, pB);
            qA = fma2(zz1[1], A0.y, qA);
            qB = fma2(zz1[5], A2.y, qB);
            pA = fma2(zz0[2], A1.x, pA);
            pB = fma2(zz0[6], A3.x, pB);
            qA = fma2(zz1[2], A1.x, qA);
            qB = fma2(zz1[6], A3.x, qB);
            pA = fma2(zz0[3], A1.y, pA);
            pB = fma2(zz0[7], A3.y, pB);
            qA = fma2(zz1[3], A1.y, qA);
            qB = fma2(zz1[7], A3.y, qB);

            float l0, u0, l1, u1;
            unpack2(add2(pA, pB), l0, u0);
            unpack2(add2(qA, qB), l1, u1);
            u64 r0 = pack2(fmaxf(l0, 0.f), fmaxf(u0, 0.f));
            u64 r1 = pack2(fmaxf(l1, 0.f), fmaxf(u1, 0.f));

            ulonglong2 C0 = w2[0], C1 = w2[1], C2 = w2[2], C3 = w2[3]; w2 += 4;
            acc0[0] = fma2(r0, C0.x, acc0[0]);
            acc1[0] = fma2(r1, C0.x, acc1[0]);
            acc0[1] = fma2(r0, C0.y, acc0[1]);
            acc1[1] = fma2(r1, C0.y, acc1[1]);
            acc0[2] = fma2(r0, C1.x, acc0[2]);
            acc1[2] = fma2(r1, C1.x, acc1[2]);
            acc0[3] = fma2(r0, C1.y, acc0[3]);
            acc1[3] = fma2(r1, C1.y, acc1[3]);
            acc0[4] = fma2(r0, C2.x, acc0[4]);
            acc1[4] = fma2(r1, C2.x, acc1[4]);
            acc0[5] = fma2(r0, C2.y, acc0[5]);
            acc1[5] = fma2(r1, C2.y, acc1[5]);
            acc0[6] = fma2(r0, C3.x, acc0[6]);
            acc1[6] = fma2(r1, C3.x, acc1[6]);
            acc0[7] = fma2(r0, C3.y, acc0[7]);
            acc1[7] = fma2(r1, C3.y, acc1[7]);
        }
    }

    // collapse pair lanes: partial_e = lo + hi
    float pa0[8], pa1[8];
    #pragma unroll
    for (int e = 0; e < 8; e++) {
        float lo, hi;
        unpack2(acc0[e], lo, hi); pa0[e] = lo + hi;
        unpack2(acc1[e], lo, hi); pa1[e] = lo + hi;
    }

    // ---- exchange: half 1 writes partials, half 0 combines + epilogue ----
    __syncthreads();                                // weights no longer needed
    float* xch = smem;                              // reuse weight region; slot stride 17
    if (half == 1) {
        float* s0 = xch + (size_t)(p * 2 + 0) * 17; // max 511*17+7 = 8694 < 34816 floats
        float* s1 = xch + (size_t)(p * 2 + 1) * 17;
        #pragma unroll
        for (int e = 0; e < 8; e++) { s0[e] = pa0[e]; s1[e] = pa1[e]; }
    }
    __syncthreads();

    if (half == 0) {
        float g2v[8], b2e[8], bb2[8];
        #pragma unroll
        for (int j = 0; j < 8; j++) {
            g2v[j] = __ldg(g2 + j);
            b2e[j] = __ldg(be2 + j);
            bb2[j] = __ldg(b2 + j);
        }
        #pragma unroll
        for (int tk = 0; tk < 2; tk++) {
            float* pa = tk ? pa1 : pa0;
            float* hh = tk ? h1 : h0;
            const float* so = xch + (size_t)(p * 2 + tk) * 17;
            float w[8]; float s2 = 0.f;
            #pragma unroll
            for (int e = 0; e < 8; e++) {
                w[e] = hh[e] + pa[e] + so[e] + bb2[e];
                s2 += w[e];
            }
            float m2 = s2 * 0.125f, v2 = 0.f;
            #pragma unroll
            for (int e = 0; e < 8; e++) { float d = w[e] - m2; v2 += d * d; }
            float inv2 = rsqrtf(v2 * 0.125f + 1e-5f);
            float o[8];
            #pragma unroll
            for (int e = 0; e < 8; e++) o[e] = (w[e] - m2) * inv2 * g2v[e] + b2e[e];
            float* op = out + (size_t)(t0 + tk) * 8;
            *(float4*)op       = make_float4(o[0], o[1], o[2], o[3]);
            *(float4*)(op + 4) = make_float4(o[4], o[5], o[6], o[7]);
        }
    }
}

extern "C" void kernel_launch(void* const* d_in, const int* in_sizes, int n_in,
                              void* d_out, int out_size) {
    const float* x      = (const float*)d_in[0];
    const float* theta  = (const float*)d_in[1];
    const float* phi    = (const float*)d_in[2];
    const float* W1     = (const float*)d_in[3];
    const float* b1     = (const float*)d_in[4];
    const float* W2     = (const float*)d_in[5];
    const float* b2     = (const float*)d_in[6];
    const float* gamma1 = (const float*)d_in[7];
    const float* beta1  = (const float*)d_in[8];
    const float* gamma2 = (const float*)d_in[9];
    const float* beta2  = (const float*)d_in[10];
    float* out = (float*)d_out;

    cudaFuncSetAttribute(qtb_kernel, cudaFuncAttributeMaxDynamicSharedMemorySize, SMEM_BYTES);
    qtb_kernel<<<128, 512, SMEM_BYTES>>>(x, theta, phi, W1, b1, W2, b2,
                                         gamma1, beta1, gamma2, beta2, out);
}